// round 3
// baseline (speedup 1.0000x reference)
#include <cuda_runtime.h>
#include <math.h>
#include <stdint.h>

#define BATCH 32
#define SEQ   8192
#define HID   512
#define CHUNKS 32                    // S-chunks per batch
#define S_PER_CHUNK (SEQ / CHUNKS)   // 256
#define NTHREADS 256
#define NWARPS   8

// Deterministic per-block partials + fan-in counters (no extra kernel).
__device__ float g_ctx_part[BATCH * CHUNKS * HID];   // 2 MB scratch
__device__ float g_sum_part[BATCH * CHUNKS];
__device__ int   g_cnt[BATCH];                       // zero-init; reset by finisher

// ---------------------------------------------------------------------------
// Single fused kernel: streams enc_out once; the last-arriving block per
// batch performs the normalization epilogue (overlapped with other batches).
// ---------------------------------------------------------------------------
__global__ __launch_bounds__(NTHREADS, 4)
void attn_main(const float* __restrict__ states_h,
               const float* __restrict__ enc_out,
               float* __restrict__ ctx_out,   // [BATCH*HID]
               float* __restrict__ w_out)     // [BATCH*SEQ]
{
    const int b     = blockIdx.x / CHUNKS;
    const int chunk = blockIdx.x % CHUNKS;
    const int tid   = threadIdx.x;
    const int w     = tid >> 5;
    const int lane  = tid & 31;

    // states_h[b] in registers: lane covers h = i*128 + lane*4 + {0..3}
    float4 sh[4];
    const float4* shp = reinterpret_cast<const float4*>(states_h + b * HID);
    #pragma unroll
    for (int i = 0; i < 4; i++) sh[i] = shp[i * 32 + lane];

    float4 ctx[4];
    #pragma unroll
    for (int i = 0; i < 4; i++) ctx[i] = make_float4(0.f, 0.f, 0.f, 0.f);
    float sum_e = 0.0f;

    const float* enc_b = enc_out + (size_t)b * SEQ * HID;
    const int s0 = chunk * S_PER_CHUNK;

    // one warp per row; 32 rows per warp; unroll 2 rows for extra MLP
    #pragma unroll 2
    for (int s = s0 + w; s < s0 + S_PER_CHUNK; s += NWARPS) {
        const float4* row = reinterpret_cast<const float4*>(enc_b + (size_t)s * HID);
        float4 v[4];
        #pragma unroll
        for (int i = 0; i < 4; i++) v[i] = __ldcs(&row[i * 32 + lane]);

        float dot = 0.0f;
        #pragma unroll
        for (int i = 0; i < 4; i++) {
            dot += v[i].x * sh[i].x + v[i].y * sh[i].y
                 + v[i].z * sh[i].z + v[i].w * sh[i].w;
        }
        #pragma unroll
        for (int off = 16; off; off >>= 1)
            dot += __shfl_xor_sync(0xFFFFFFFFu, dot, off);

        const float e = __expf(dot * (1.0f / 512.0f));
        if (lane == 0) {
            w_out[(size_t)b * SEQ + s] = e;      // unnormalized; finisher rescales
            sum_e += e;
        }
        #pragma unroll
        for (int i = 0; i < 4; i++) {
            ctx[i].x = fmaf(e, v[i].x, ctx[i].x);
            ctx[i].y = fmaf(e, v[i].y, ctx[i].y);
            ctx[i].z = fmaf(e, v[i].z, ctx[i].z);
            ctx[i].w = fmaf(e, v[i].w, ctx[i].w);
        }
    }

    // ---- cross-warp context reduction in smem, write block partials ----
    __shared__ float4 s_ctx[NWARPS][HID / 4];   // 16 KB
    __shared__ float  s_sum[NWARPS];
    #pragma unroll
    for (int i = 0; i < 4; i++) s_ctx[w][i * 32 + lane] = ctx[i];
    if (lane == 0) s_sum[w] = sum_e;
    __syncthreads();

    {
        const float2* sc = reinterpret_cast<const float2*>(&s_ctx[0][0]);
        const int stride2 = HID / 2;
        float2 acc = make_float2(0.f, 0.f);
        #pragma unroll
        for (int ww = 0; ww < NWARPS; ww++) {
            float2 t = sc[ww * stride2 + tid];
            acc.x += t.x; acc.y += t.y;
        }
        float2* dst = reinterpret_cast<float2*>(
            g_ctx_part + ((size_t)b * CHUNKS + chunk) * HID);
        dst[tid] = acc;
    }
    if (tid == 0) {
        float t = 0.f;
        #pragma unroll
        for (int ww = 0; ww < NWARPS; ww++) t += s_sum[ww];
        g_sum_part[b * CHUNKS + chunk] = t;
    }

    // ---- fan-in: last-arriving block of this batch runs the epilogue ----
    __shared__ int s_last;
    __threadfence();                       // publish partials + w_out
    __syncthreads();                       // ensure partial writes issued by all
    if (tid == 0) {
        int old = atomicAdd(&g_cnt[b], 1);
        s_last = (old == CHUNKS - 1);
    }
    __syncthreads();
    if (!s_last) return;

    // ===================== finisher path (one block per batch) =============
    __shared__ float s_inv;
    if (tid < 32) {
        float v = g_sum_part[b * CHUNKS + tid];
        #pragma unroll
        for (int off = 16; off; off >>= 1)
            v += __shfl_xor_sync(0xFFFFFFFFu, v, off);
        if (tid == 0) s_inv = __frcp_rn(v);
    }
    __syncthreads();
    const float inv = s_inv;

    // normalize weights: 8192 floats = 2048 float4; 8 float4 per thread
    {
        float4* wp = reinterpret_cast<float4*>(w_out + (size_t)b * SEQ);
        #pragma unroll
        for (int i = 0; i < SEQ / 4 / NTHREADS; i++) {
            float4 t = wp[i * NTHREADS + tid];
            t.x *= inv; t.y *= inv; t.z *= inv; t.w *= inv;
            wp[i * NTHREADS + tid] = t;
        }
    }

    // reduce + normalize context: h = tid and tid+256
    #pragma unroll
    for (int r = 0; r < HID / NTHREADS; r++) {
        const int h = r * NTHREADS + tid;
        float acc = 0.0f;
        #pragma unroll
        for (int c = 0; c < CHUNKS; c++)
            acc += g_ctx_part[((size_t)b * CHUNKS + c) * HID + h];
        ctx_out[b * HID + h] = acc * inv;
    }

    if (tid == 0) g_cnt[b] = 0;            // reset for next graph replay
}

// ---------------------------------------------------------------------------
extern "C" void kernel_launch(void* const* d_in, const int* in_sizes, int n_in,
                              void* d_out, int out_size)
{
    const float* states_h = nullptr;
    const float* enc_out  = nullptr;
    for (int i = 0; i < n_in; i++) {
        if (in_sizes[i] == BATCH * HID)            states_h = (const float*)d_in[i];
        else if ((int64_t)in_sizes[i] == (int64_t)BATCH * SEQ * HID)
                                                   enc_out  = (const float*)d_in[i];
    }

    float* ctx_out = (float*)d_out;                 // [context | weights]
    float* w_out   = (float*)d_out + BATCH * HID;

    attn_main<<<BATCH * CHUNKS, NTHREADS>>>(states_h, enc_out, ctx_out, w_out);
}

// round 4
// speedup vs baseline: 1.0473x; 1.0473x over previous
#include <cuda_runtime.h>
#include <math.h>
#include <stdint.h>

#define BATCH 32
#define SEQ   8192
#define HID   512
#define CHUNKS 37                    // 32*37 = 1184 = 2 * (148 SMs * 4 blocks) exactly
#define NTHREADS 256
#define NWARPS   8

// Deterministic per-block partials (no atomics, no fences).
__device__ float g_ctx_part[BATCH * CHUNKS * HID];   // ~2.4 MB scratch
__device__ float g_sum_part[BATCH * CHUNKS];

// ---------------------------------------------------------------------------
// Kernel 1: fused single-pass — streams enc_out exactly once.
// grid = 1184 blocks = exactly 2 full waves at 4 blocks/SM.
// ---------------------------------------------------------------------------
__global__ __launch_bounds__(NTHREADS, 4)
void attn_main(const float* __restrict__ states_h,
               const float* __restrict__ enc_out,
               float* __restrict__ w_out)     // [BATCH*SEQ] unnormalized
{
    const int b     = blockIdx.x / CHUNKS;
    const int chunk = blockIdx.x % CHUNKS;
    const int tid   = threadIdx.x;
    const int w     = tid >> 5;
    const int lane  = tid & 31;

    // balanced chunk bounds: 221 or 222 rows
    const int s_begin = (chunk * SEQ) / CHUNKS;
    const int s_end   = ((chunk + 1) * SEQ) / CHUNKS;

    // states_h[b] in registers: lane covers h = i*128 + lane*4 + {0..3}
    float4 sh[4];
    const float4* shp = reinterpret_cast<const float4*>(states_h + b * HID);
    #pragma unroll
    for (int i = 0; i < 4; i++) sh[i] = shp[i * 32 + lane];

    float4 ctx[4];
    #pragma unroll
    for (int i = 0; i < 4; i++) ctx[i] = make_float4(0.f, 0.f, 0.f, 0.f);
    float sum_e = 0.0f;

    const float* enc_b = enc_out + (size_t)b * SEQ * HID;

    // one warp per row, stride NWARPS; unroll 2 for MLP
    #pragma unroll 2
    for (int s = s_begin + w; s < s_end; s += NWARPS) {
        const float4* row = reinterpret_cast<const float4*>(enc_b + (size_t)s * HID);
        float4 v[4];
        #pragma unroll
        for (int i = 0; i < 4; i++) v[i] = __ldcs(&row[i * 32 + lane]);

        float dot = 0.0f;
        #pragma unroll
        for (int i = 0; i < 4; i++) {
            dot += v[i].x * sh[i].x + v[i].y * sh[i].y
                 + v[i].z * sh[i].z + v[i].w * sh[i].w;
        }
        #pragma unroll
        for (int off = 16; off; off >>= 1)
            dot += __shfl_xor_sync(0xFFFFFFFFu, dot, off);

        const float e = __expf(dot * (1.0f / 512.0f));
        if (lane == 0) {
            w_out[(size_t)b * SEQ + s] = e;
            sum_e += e;
        }
        #pragma unroll
        for (int i = 0; i < 4; i++) {
            ctx[i].x = fmaf(e, v[i].x, ctx[i].x);
            ctx[i].y = fmaf(e, v[i].y, ctx[i].y);
            ctx[i].z = fmaf(e, v[i].z, ctx[i].z);
            ctx[i].w = fmaf(e, v[i].w, ctx[i].w);
        }
    }

    // ---- cross-warp context reduction in smem, write block partials ----
    __shared__ float4 s_ctx[NWARPS][HID / 4];   // 16 KB
    __shared__ float  s_sum[NWARPS];
    #pragma unroll
    for (int i = 0; i < 4; i++) s_ctx[w][i * 32 + lane] = ctx[i];
    if (lane == 0) s_sum[w] = sum_e;
    __syncthreads();

    {
        const float2* sc = reinterpret_cast<const float2*>(&s_ctx[0][0]);
        const int stride2 = HID / 2;
        float2 acc = make_float2(0.f, 0.f);
        #pragma unroll
        for (int ww = 0; ww < NWARPS; ww++) {
            float2 t = sc[ww * stride2 + tid];
            acc.x += t.x; acc.y += t.y;
        }
        float2* dst = reinterpret_cast<float2*>(
            g_ctx_part + ((size_t)b * CHUNKS + chunk) * HID);
        dst[tid] = acc;
    }
    if (tid == 0) {
        float t = 0.f;
        #pragma unroll
        for (int ww = 0; ww < NWARPS; ww++) t += s_sum[ww];
        g_sum_part[b * CHUNKS + chunk] = t;
    }
}

// ---------------------------------------------------------------------------
// Kernel 2: epilogue, high-parallelism.
// grid = BATCH*8 (w-normalize, 1 float4/thread) + BATCH (ctx reduce).
// Every block independently re-derives its batch's inv-sum (37 L2-hit loads).
// ---------------------------------------------------------------------------
#define WSLICES 8    // SEQ/(NTHREADS*4) = 8192/1024

__global__ __launch_bounds__(NTHREADS)
void attn_epilogue(float* __restrict__ ctx_out,   // [BATCH*HID]
                   float* __restrict__ w_out)     // [BATCH*SEQ]
{
    const bool is_ctx = blockIdx.x >= BATCH * WSLICES;
    const int  b      = is_ctx ? (blockIdx.x - BATCH * WSLICES)
                               : (blockIdx.x / WSLICES);
    const int  tid    = threadIdx.x;

    // inv-sum for this batch: 37 partials, reduced by warp 0
    __shared__ float s_inv;
    if (tid < 32) {
        const float* sp = g_sum_part + b * CHUNKS;
        float v = sp[tid];
        if (tid + 32 < CHUNKS) v += sp[tid + 32];
        #pragma unroll
        for (int off = 16; off; off >>= 1)
            v += __shfl_xor_sync(0xFFFFFFFFu, v, off);
        if (tid == 0) s_inv = __frcp_rn(v);
    }
    __syncthreads();
    const float inv = s_inv;

    if (!is_ctx) {
        const int slice = blockIdx.x % WSLICES;
        float4* wp = reinterpret_cast<float4*>(w_out + (size_t)b * SEQ) +
                     slice * NTHREADS;
        float4 t = wp[tid];
        t.x *= inv; t.y *= inv; t.z *= inv; t.w *= inv;
        wp[tid] = t;
    } else {
        // ctx reduce: 2 h per thread, 37 partials each (L2-resident scratch)
        #pragma unroll
        for (int r = 0; r < HID / NTHREADS; r++) {
            const int h = r * NTHREADS + tid;
            float acc = 0.0f;
            #pragma unroll
            for (int c = 0; c < CHUNKS; c++)
                acc += g_ctx_part[((size_t)b * CHUNKS + c) * HID + h];
            ctx_out[b * HID + h] = acc * inv;
        }
    }
}

// ---------------------------------------------------------------------------
extern "C" void kernel_launch(void* const* d_in, const int* in_sizes, int n_in,
                              void* d_out, int out_size)
{
    const float* states_h = nullptr;
    const float* enc_out  = nullptr;
    for (int i = 0; i < n_in; i++) {
        if (in_sizes[i] == BATCH * HID)            states_h = (const float*)d_in[i];
        else if ((int64_t)in_sizes[i] == (int64_t)BATCH * SEQ * HID)
                                                   enc_out  = (const float*)d_in[i];
    }

    float* ctx_out = (float*)d_out;                 // [context | weights]
    float* w_out   = (float*)d_out + BATCH * HID;

    attn_main<<<BATCH * CHUNKS, NTHREADS>>>(states_h, enc_out, w_out);
    attn_epilogue<<<BATCH * WSLICES + BATCH, NTHREADS>>>(ctx_out, w_out);
}